// round 5
// baseline (speedup 1.0000x reference)
#include <cuda_runtime.h>
#include <cstdint>

// LDDMM variational shooting RHS, Gaussian kernel sigma=0.1, B=1, N=8192, D=3.
//
// dcp_i  = sum_j exp(-50*|xi-xj|^2) * p_j                    (p = clamp(mom,-1,1))
// dmom_i = 100 * sum_j K_ij (p_i.p_j) (x_i - x_j)
//
// Strategy: O(N^2) pairwise, exp computed as exp2 polynomial on the FMA pipe
// (avoids the MUFU ceiling ~500us), with fma.rn.f32x2 packing 2 j-points per
// instruction. j-range split across blockIdx.y into partials (deterministic,
// no atomics), reduced by a second kernel.

#define THREADS 128
#define IPT     2                 // i-points per thread
#define ISPAN   (THREADS * IPT)   // 256 i per block
#define JTILE   512               // j per block (one shared tile)
#define JT2     (JTILE / 2)       // packed pairs in tile
#define MAXN    16384
#define MAXG    ((MAXN + JTILE - 1) / JTILE)

// partial[g][i*6 + 0..2] = dcp partial, [3..5] = sum w*(xj-xi) partial
__device__ float g_part[MAXG][MAXN * 6];

using u64 = unsigned long long;

__device__ __forceinline__ u64 pk2(float a, float b) {
    u64 r; asm("mov.b64 %0, {%1, %2};" : "=l"(r) : "f"(a), "f"(b)); return r;
}
__device__ __forceinline__ void upk2(u64 v, float& a, float& b) {
    asm("mov.b64 {%0, %1}, %2;" : "=f"(a), "=f"(b) : "l"(v));
}
__device__ __forceinline__ u64 f2add(u64 a, u64 b) {
    u64 r; asm("add.rn.f32x2 %0, %1, %2;" : "=l"(r) : "l"(a), "l"(b)); return r;
}
__device__ __forceinline__ u64 f2mul(u64 a, u64 b) {
    u64 r; asm("mul.rn.f32x2 %0, %1, %2;" : "=l"(r) : "l"(a), "l"(b)); return r;
}
__device__ __forceinline__ u64 f2fma(u64 a, u64 b, u64 c) {
    u64 r; asm("fma.rn.f32x2 %0, %1, %2, %3;" : "=l"(r) : "l"(a), "l"(b), "l"(c)); return r;
}

__device__ __forceinline__ float clamp1(float v) {
    return fminf(fmaxf(v, -1.0f), 1.0f);
}

// exp(-50*d2) = 2^(C*d2), C = -50*log2(e)
#define EXPC  (-72.13475204444817f)
#define MAGIC (12582912.0f)        // 1.5 * 2^23
#define KADD  (127 - 0x4B400000)   // (bits(fz)+KADD)<<23 = exponent scale bits

__global__ __launch_bounds__(THREADS)
void lddmm_main(const float* __restrict__ mom, const float* __restrict__ x, int N)
{
    __shared__ float4 sA[JT2];  // (xj0, xj1, yj0, yj1)
    __shared__ float4 sB[JT2];  // (zj0, zj1, px0, px1)
    __shared__ float4 sC[JT2];  // (py0, py1, pz0, pz1)

    const int t  = threadIdx.x;
    const int bi = blockIdx.x;
    const int g  = blockIdx.y;
    const int jbase = g * JTILE;

    // ---- load j tile (padding: x=0, p=0 -> zero contribution) ----
    for (int k = t; k < JT2; k += THREADS) {
        int j0 = jbase + 2 * k, j1 = j0 + 1;
        float X0 = 0.f, Y0 = 0.f, Z0 = 0.f, P0 = 0.f, Q0 = 0.f, R0 = 0.f;
        float X1 = 0.f, Y1 = 0.f, Z1 = 0.f, P1 = 0.f, Q1 = 0.f, R1 = 0.f;
        if (j0 < N) {
            X0 = x[3 * j0]; Y0 = x[3 * j0 + 1]; Z0 = x[3 * j0 + 2];
            P0 = clamp1(mom[3 * j0]); Q0 = clamp1(mom[3 * j0 + 1]); R0 = clamp1(mom[3 * j0 + 2]);
        }
        if (j1 < N) {
            X1 = x[3 * j1]; Y1 = x[3 * j1 + 1]; Z1 = x[3 * j1 + 2];
            P1 = clamp1(mom[3 * j1]); Q1 = clamp1(mom[3 * j1 + 1]); R1 = clamp1(mom[3 * j1 + 2]);
        }
        sA[k] = make_float4(X0, X1, Y0, Y1);
        sB[k] = make_float4(Z0, Z1, P0, P1);
        sC[k] = make_float4(Q0, Q1, R0, R1);
    }
    __syncthreads();

    // ---- per-thread i registers (broadcast packed) ----
    u64 nxi[IPT], nyi[IPT], nzi[IPT];   // packed (-xi, -xi)
    u64 pxi[IPT], pyi[IPT], pzi[IPT];   // packed (pi, pi)
    u64 adx[IPT], ady[IPT], adz[IPT];   // sum w*(xj-xi)
    u64 acx[IPT], acy[IPT], acz[IPT];   // sum e*pj

    const int i0 = bi * ISPAN + t * IPT;
#pragma unroll
    for (int ii = 0; ii < IPT; ii++) {
        int i = i0 + ii;
        float X = 0.f, Y = 0.f, Z = 0.f, P = 0.f, Q = 0.f, R = 0.f;
        if (i < N) {
            X = x[3 * i]; Y = x[3 * i + 1]; Z = x[3 * i + 2];
            P = clamp1(mom[3 * i]); Q = clamp1(mom[3 * i + 1]); R = clamp1(mom[3 * i + 2]);
        }
        nxi[ii] = pk2(-X, -X); nyi[ii] = pk2(-Y, -Y); nzi[ii] = pk2(-Z, -Z);
        pxi[ii] = pk2(P, P);   pyi[ii] = pk2(Q, Q);   pzi[ii] = pk2(R, R);
        adx[ii] = 0ull; ady[ii] = 0ull; adz[ii] = 0ull;
        acx[ii] = 0ull; acy[ii] = 0ull; acz[ii] = 0ull;
    }

    // packed constants
    const u64 C2    = pk2(EXPC, EXPC);
    const u64 MAG2  = pk2(MAGIC, MAGIC);
    const u64 NMAG2 = pk2(-MAGIC, -MAGIC);
    const u64 NONE2 = pk2(-1.0f, -1.0f);
    const u64 ONE2  = pk2(1.0f, 1.0f);
    // 2^f Taylor deg-5 on [-0.5, 0.5]: rel err < 3e-6
    const u64 K5 = pk2(1.3333558e-3f, 1.3333558e-3f);
    const u64 K4 = pk2(9.6181291e-3f, 9.6181291e-3f);
    const u64 K3 = pk2(5.5504109e-2f, 5.5504109e-2f);
    const u64 K2 = pk2(2.4022651e-1f, 2.4022651e-1f);
    const u64 K1 = pk2(6.9314718e-1f, 6.9314718e-1f);

    // ---- main pairwise loop: each iter = 2 j-points x IPT i-points ----
#pragma unroll 2
    for (int k = 0; k < JT2; k++) {
        float4 a = sA[k], b = sB[k], c = sC[k];
        u64 xj = pk2(a.x, a.y), yj = pk2(a.z, a.w), zj = pk2(b.x, b.y);
        u64 qx = pk2(b.z, b.w), qy = pk2(c.x, c.y), qz = pk2(c.z, c.w);
#pragma unroll
        for (int ii = 0; ii < IPT; ii++) {
            u64 dx = f2add(xj, nxi[ii]);
            u64 dy = f2add(yj, nyi[ii]);
            u64 dz = f2add(zj, nzi[ii]);
            u64 d2 = f2mul(dx, dx);
            d2 = f2fma(dy, dy, d2);
            d2 = f2fma(dz, dz, d2);
            u64 tt = f2mul(d2, C2);            // t = -72.1347*d2 <= 0
            float t0, t1; upk2(tt, t0, t1);
            t0 = fmaxf(t0, -126.0f);           // underflow clamp keeps magic trick exact
            t1 = fmaxf(t1, -126.0f);
            tt = pk2(t0, t1);
            u64 fz = f2add(tt, MAG2);          // round-to-nearest integer part
            u64 nn = f2add(fz, NMAG2);         // n = rint(t)
            u64 ff = f2fma(nn, NONE2, tt);     // f = t - n in [-0.5, 0.5]
            u64 p  = f2fma(K5, ff, K4);
            p = f2fma(p, ff, K3);
            p = f2fma(p, ff, K2);
            p = f2fma(p, ff, K1);
            p = f2fma(p, ff, ONE2);            // 2^f
            float fz0, fz1; upk2(fz, fz0, fz1);
            int s0 = (__float_as_int(fz0) + KADD) << 23;   // (n+127)<<23
            int s1 = (__float_as_int(fz1) + KADD) << 23;
            float p0, p1; upk2(p, p0, p1);
            float e0 = p0 * __int_as_float(s0);
            float e1 = p1 * __int_as_float(s1);
            u64 e = pk2(e0, e1);               // K_ij = 2^t

            u64 pp = f2mul(pxi[ii], qx);
            pp = f2fma(pyi[ii], qy, pp);
            pp = f2fma(pzi[ii], qz, pp);       // p_i . p_j
            u64 w = f2mul(e, pp);              // W_ij

            acx[ii] = f2fma(e, qx, acx[ii]);
            acy[ii] = f2fma(e, qy, acy[ii]);
            acz[ii] = f2fma(e, qz, acz[ii]);
            adx[ii] = f2fma(w, dx, adx[ii]);
            ady[ii] = f2fma(w, dy, ady[ii]);
            adz[ii] = f2fma(w, dz, adz[ii]);
        }
    }

    // ---- write partials (one writer per slot: deterministic) ----
#pragma unroll
    for (int ii = 0; ii < IPT; ii++) {
        int i = i0 + ii;
        if (i < N) {
            float u, v, cxs, cys, czs, gxs, gys, gzs;
            upk2(acx[ii], u, v); cxs = u + v;
            upk2(acy[ii], u, v); cys = u + v;
            upk2(acz[ii], u, v); czs = u + v;
            upk2(adx[ii], u, v); gxs = u + v;
            upk2(ady[ii], u, v); gys = u + v;
            upk2(adz[ii], u, v); gzs = u + v;
            float* P = &g_part[g][i * 6];
            P[0] = cxs; P[1] = cys; P[2] = czs;
            P[3] = gxs; P[4] = gys; P[5] = gzs;
        }
    }
}

__global__ void lddmm_reduce(float* __restrict__ out, int N, int G)
{
    int idx = blockIdx.x * blockDim.x + threadIdx.x;  // over N*3
    if (idx >= N * 3) return;
    int i = idx / 3, c = idx % 3;
    float sd = 0.f, sg = 0.f;
    for (int g = 0; g < G; g++) {
        sd += g_part[g][i * 6 + c];
        sg += g_part[g][i * 6 + 3 + c];
    }
    // partials accumulated w*(xj - xi); dmom = 100 * sum w*(xi - xj) = -100*sg
    out[idx]         = -100.0f * sg;   // dmom
    out[N * 3 + idx] = sd;             // dcp
}

extern "C" void kernel_launch(void* const* d_in, const int* in_sizes, int n_in,
                              void* d_out, int out_size)
{
    const float* mom = (const float*)d_in[0];
    const float* x   = (const float*)d_in[1];
    int N = in_sizes[0] / 3;
    if (N <= 0) return;
    if (N > MAXN) N = MAXN;  // scratch bound (problem uses N=8192)

    int G   = (N + JTILE - 1) / JTILE;
    int NBI = (N + ISPAN - 1) / ISPAN;
    dim3 grid(NBI, G);
    lddmm_main<<<grid, THREADS>>>(mom, x, N);

    int tot = N * 3;
    lddmm_reduce<<<(tot + 255) / 256, 256>>>((float*)d_out, N, G);
}

// round 6
// speedup vs baseline: 1.1664x; 1.1664x over previous
#include <cuda_runtime.h>
#include <cstdint>

// LDDMM variational shooting RHS, Gaussian kernel sigma=0.1, B=1, N=8192, D=3.
//
// dcp_i  = sum_j exp(-50*|xi-xj|^2) * p_j                    (p = clamp(mom,-1,1))
// dmom_i = 100 * sum_j K_ij (p_i.p_j) (x_i - x_j)
//
// O(N^2) pairwise on the FMA pipe with fma.rn.f32x2 (2 j-points per instr).
// exp(-50 d2) = 2^(-d2') with coordinates pre-scaled by s = sqrt(50*log2 e),
// computed via magic-number range reduction + deg-4 economized polynomial
// (no MUFU). j-range split across blockIdx.y into deterministic partials
// ([g][dim][i] layout, coalesced), reduced by a second kernel.

#define THREADS 128
#define IPT     2                 // i-points per thread
#define ISPAN   (THREADS * IPT)   // 256 i per block
#define JTILE   256               // j per block (grid.y doubled vs JTILE=512 for wave balance)
#define JT2     (JTILE / 2)       // packed pairs in tile
#define MAXN    16384
#define MAXG    ((MAXN + JTILE - 1) / JTILE)

// coordinate prescale: s^2 = 50*log2(e) = 72.13475204
#define SSCALE  8.4932180f
#define MAGIC   12582912.0f        // 1.5 * 2^23

// partials: g_part[g][d*MAXN + i], d=0..2 dcp, d=3..5 sum w*(xj-xi) (scaled)
__device__ __align__(16) float g_part[MAXG][6 * MAXN];

using u64 = unsigned long long;

__device__ __forceinline__ u64 pk2(float a, float b) {
    u64 r; asm("mov.b64 %0, {%1, %2};" : "=l"(r) : "f"(a), "f"(b)); return r;
}
__device__ __forceinline__ void upk2(u64 v, float& a, float& b) {
    asm("mov.b64 {%0, %1}, %2;" : "=f"(a), "=f"(b) : "l"(v));
}
__device__ __forceinline__ u64 f2add(u64 a, u64 b) {
    u64 r; asm("add.rn.f32x2 %0, %1, %2;" : "=l"(r) : "l"(a), "l"(b)); return r;
}
__device__ __forceinline__ u64 f2mul(u64 a, u64 b) {
    u64 r; asm("mul.rn.f32x2 %0, %1, %2;" : "=l"(r) : "l"(a), "l"(b)); return r;
}
__device__ __forceinline__ u64 f2fma(u64 a, u64 b, u64 c) {
    u64 r; asm("fma.rn.f32x2 %0, %1, %2, %3;" : "=l"(r) : "l"(a), "l"(b), "l"(c)); return r;
}

__device__ __forceinline__ float clamp1(float v) {
    return fminf(fmaxf(v, -1.0f), 1.0f);
}

__global__ __launch_bounds__(THREADS)
void lddmm_main(const float* __restrict__ mom, const float* __restrict__ x, int N)
{
    __shared__ float4 sA[JT2];  // (xj0, xj1, yj0, yj1)   scaled coords
    __shared__ float4 sB[JT2];  // (zj0, zj1, px0, px1)
    __shared__ float4 sC[JT2];  // (py0, py1, pz0, pz1)

    const int t  = threadIdx.x;
    const int bi = blockIdx.x;
    const int g  = blockIdx.y;
    const int jbase = g * JTILE;

    // ---- load j tile (padding: x=0 (clamped exp), p=0 -> zero contribution) ----
    for (int k = t; k < JT2; k += THREADS) {
        int j0 = jbase + 2 * k, j1 = j0 + 1;
        float X0 = 0.f, Y0 = 0.f, Z0 = 0.f, P0 = 0.f, Q0 = 0.f, R0 = 0.f;
        float X1 = 0.f, Y1 = 0.f, Z1 = 0.f, P1 = 0.f, Q1 = 0.f, R1 = 0.f;
        if (j0 < N) {
            X0 = x[3 * j0] * SSCALE; Y0 = x[3 * j0 + 1] * SSCALE; Z0 = x[3 * j0 + 2] * SSCALE;
            P0 = clamp1(mom[3 * j0]); Q0 = clamp1(mom[3 * j0 + 1]); R0 = clamp1(mom[3 * j0 + 2]);
        }
        if (j1 < N) {
            X1 = x[3 * j1] * SSCALE; Y1 = x[3 * j1 + 1] * SSCALE; Z1 = x[3 * j1 + 2] * SSCALE;
            P1 = clamp1(mom[3 * j1]); Q1 = clamp1(mom[3 * j1 + 1]); R1 = clamp1(mom[3 * j1 + 2]);
        }
        sA[k] = make_float4(X0, X1, Y0, Y1);
        sB[k] = make_float4(Z0, Z1, P0, P1);
        sC[k] = make_float4(Q0, Q1, R0, R1);
    }
    __syncthreads();

    // ---- per-thread i registers (broadcast packed); split-stride i for coalesced stores ----
    u64 nxi[IPT], nyi[IPT], nzi[IPT];   // packed (-xi_s, -xi_s)
    u64 pxi[IPT], pyi[IPT], pzi[IPT];   // packed (pi, pi)
    u64 adx[IPT], ady[IPT], adz[IPT];   // sum w*(xj_s - xi_s)
    u64 acx[IPT], acy[IPT], acz[IPT];   // sum e*pj

    const int i0 = bi * ISPAN + t;
#pragma unroll
    for (int ii = 0; ii < IPT; ii++) {
        int i = i0 + ii * THREADS;
        float X = 0.f, Y = 0.f, Z = 0.f, P = 0.f, Q = 0.f, R = 0.f;
        if (i < N) {
            X = x[3 * i] * SSCALE; Y = x[3 * i + 1] * SSCALE; Z = x[3 * i + 2] * SSCALE;
            P = clamp1(mom[3 * i]); Q = clamp1(mom[3 * i + 1]); R = clamp1(mom[3 * i + 2]);
        }
        nxi[ii] = pk2(-X, -X); nyi[ii] = pk2(-Y, -Y); nzi[ii] = pk2(-Z, -Z);
        pxi[ii] = pk2(P, P);   pyi[ii] = pk2(Q, Q);   pzi[ii] = pk2(R, R);
        adx[ii] = 0ull; ady[ii] = 0ull; adz[ii] = 0ull;
        acx[ii] = 0ull; acy[ii] = 0ull; acz[ii] = 0ull;
    }

    // packed constants
    const u64 MAG2  = pk2(MAGIC, MAGIC);
    const u64 NMAG2 = pk2(-MAGIC, -MAGIC);
    const u64 NONE2 = pk2(-1.0f, -1.0f);
    const u64 ONE2  = pk2(1.0f, 1.0f);
    // 2^(-f) on f in [-0.5,0.5]: deg-4, Chebyshev-economized from deg-5 Taylor
    //   2^(-f) ~= 1 - c1 f + c2 f^2 - c3 f^3 + c4 f^4, max err ~5e-6
    const u64 C4_2  = pk2( 0.00961813f,  0.00961813f);
    const u64 NC3_2 = pk2(-0.05592078f, -0.05592078f);
    const u64 C2_2  = pk2( 0.24022651f,  0.24022651f);
    const u64 NC1_2 = pk2(-0.69312114f, -0.69312114f);

    // ---- main pairwise loop: each iter = 2 j-points x IPT i-points ----
#pragma unroll 2
    for (int k = 0; k < JT2; k++) {
        float4 a = sA[k], b = sB[k], c = sC[k];
        u64 xj = pk2(a.x, a.y), yj = pk2(a.z, a.w), zj = pk2(b.x, b.y);
        u64 qx = pk2(b.z, b.w), qy = pk2(c.x, c.y), qz = pk2(c.z, c.w);
#pragma unroll
        for (int ii = 0; ii < IPT; ii++) {
            u64 dx = f2add(xj, nxi[ii]);            // scaled deltas
            u64 dy = f2add(yj, nyi[ii]);
            u64 dz = f2add(zj, nzi[ii]);
            u64 d2 = f2mul(dx, dx);
            d2 = f2fma(dy, dy, d2);
            d2 = f2fma(dz, dz, d2);                 // d2' = 72.1347 * |dx|^2 >= 0
            float d0, d1; upk2(d2, d0, d1);
            d0 = fminf(d0, 125.0f);                 // keep 2^-n normal (underflow guard)
            d1 = fminf(d1, 125.0f);
            u64 d2c = pk2(d0, d1);
            u64 fz = f2add(d2c, MAG2);              // magic round: bits hold n = rint(d2')
            u64 nn = f2add(fz, NMAG2);              // n as float
            u64 ff = f2fma(nn, NONE2, d2c);         // f = d2' - n in [-0.5, 0.5]
            u64 p  = f2fma(C4_2, ff, NC3_2);        // 2^(-f)
            p = f2fma(p, ff, C2_2);
            p = f2fma(p, ff, NC1_2);
            p = f2fma(p, ff, ONE2);
            float fz0, fz1; upk2(fz, fz0, fz1);
            int s0i = 0x3F800000 - (__float_as_int(fz0) << 23);   // (127-n)<<23
            int s1i = 0x3F800000 - (__float_as_int(fz1) << 23);
            u64 s2 = pk2(__int_as_float(s0i), __int_as_float(s1i));
            u64 e = f2mul(p, s2);                   // K_ij = 2^(-d2')

            u64 pp = f2mul(pxi[ii], qx);
            pp = f2fma(pyi[ii], qy, pp);
            pp = f2fma(pzi[ii], qz, pp);            // p_i . p_j
            u64 w = f2mul(e, pp);                   // W_ij

            acx[ii] = f2fma(e, qx, acx[ii]);
            acy[ii] = f2fma(e, qy, acy[ii]);
            acz[ii] = f2fma(e, qz, acz[ii]);
            adx[ii] = f2fma(w, dx, adx[ii]);
            ady[ii] = f2fma(w, dy, ady[ii]);
            adz[ii] = f2fma(w, dz, adz[ii]);
        }
    }

    // ---- write partials, coalesced [g][d][i] layout (one writer per slot) ----
#pragma unroll
    for (int ii = 0; ii < IPT; ii++) {
        int i = i0 + ii * THREADS;
        if (i < N) {
            float u, v;
            float* P = g_part[g];
            upk2(acx[ii], u, v); P[0 * MAXN + i] = u + v;
            upk2(acy[ii], u, v); P[1 * MAXN + i] = u + v;
            upk2(acz[ii], u, v); P[2 * MAXN + i] = u + v;
            upk2(adx[ii], u, v); P[3 * MAXN + i] = u + v;
            upk2(ady[ii], u, v); P[4 * MAXN + i] = u + v;
            upk2(adz[ii], u, v); P[5 * MAXN + i] = u + v;
        }
    }
}

__global__ void lddmm_reduce(float* __restrict__ out, int N, int G)
{
    // dmom = 100 * sum w*(xi-xj) = -(100/s) * adx_sum  (coords were pre-scaled by s)
    const float DSC = -100.0f / SSCALE;
    int idx = blockIdx.x * blockDim.x + threadIdx.x;
    if ((N & 3) == 0) {
        int n4 = N >> 2;
        if (idx >= 6 * n4) return;
        int d = idx / n4, i4 = idx - d * n4;
        const float* base = &g_part[0][d * MAXN] + i4 * 4;
        float4 s = make_float4(0.f, 0.f, 0.f, 0.f);
        for (int g = 0; g < G; g++) {
            float4 v = *(const float4*)(base + (size_t)g * 6 * MAXN);
            s.x += v.x; s.y += v.y; s.z += v.z; s.w += v.w;
        }
        int i0 = i4 * 4;
        if (d < 3) {  // dcp at out[3N + i*3 + d]
            out[3 * N + (i0 + 0) * 3 + d] = s.x;
            out[3 * N + (i0 + 1) * 3 + d] = s.y;
            out[3 * N + (i0 + 2) * 3 + d] = s.z;
            out[3 * N + (i0 + 3) * 3 + d] = s.w;
        } else {      // dmom at out[i*3 + c]
            int c = d - 3;
            out[(i0 + 0) * 3 + c] = s.x * DSC;
            out[(i0 + 1) * 3 + c] = s.y * DSC;
            out[(i0 + 2) * 3 + c] = s.z * DSC;
            out[(i0 + 3) * 3 + c] = s.w * DSC;
        }
    } else {
        if (idx >= 6 * N) return;
        int d = idx / N, i = idx - d * N;
        float s = 0.f;
        for (int g = 0; g < G; g++) s += g_part[g][d * MAXN + i];
        if (d < 3) out[3 * N + i * 3 + d] = s;
        else       out[i * 3 + (d - 3)]   = s * DSC;
    }
}

extern "C" void kernel_launch(void* const* d_in, const int* in_sizes, int n_in,
                              void* d_out, int out_size)
{
    const float* mom = (const float*)d_in[0];
    const float* x   = (const float*)d_in[1];
    int N = in_sizes[0] / 3;
    if (N <= 0) return;
    if (N > MAXN) N = MAXN;  // scratch bound (problem uses N=8192)

    int G   = (N + JTILE - 1) / JTILE;
    int NBI = (N + ISPAN - 1) / ISPAN;
    dim3 grid(NBI, G);
    lddmm_main<<<grid, THREADS>>>(mom, x, N);

    int tot = ((N & 3) == 0) ? (6 * (N >> 2)) : (6 * N);
    lddmm_reduce<<<(tot + 255) / 256, 256>>>((float*)d_out, N, G);
}